// round 8
// baseline (speedup 1.0000x reference)
#include <cuda_runtime.h>
#include <cuda_bf16.h>
#include <cstdint>

using bf16 = __nv_bfloat16;

#define NB   4
#define SQL  2048
#define SKL  2048
#define DIM  512
#define RAD  128
#define NREL 257
#define NRELP 384   // padded

// ---------------- device scratch ----------------
__device__ float g_qrel[(size_t)NB * SQL * NRELP];
__device__ bf16 g_Qh[(size_t)NB * SQL * DIM];
__device__ bf16 g_Ql[(size_t)NB * SQL * DIM];
__device__ bf16 g_Kh[(size_t)NB * SKL * DIM];
__device__ bf16 g_Kl[(size_t)NB * SKL * DIM];
__device__ bf16 g_REh[(size_t)NRELP * DIM];
__device__ bf16 g_REl[(size_t)NRELP * DIM];
__device__ bf16 g_Vth[(size_t)NB * DIM * SKL];   // V transposed: [b][n][k]
__device__ bf16 g_Vtl[(size_t)NB * DIM * SKL];
__device__ bf16 g_Ah[(size_t)NB * SQL * SKL];    // attn split
__device__ bf16 g_Al[(size_t)NB * SQL * SKL];

// ---------------- helpers ----------------
__device__ __forceinline__ uint32_t smem_u32(const void* p) {
    return (uint32_t)__cvta_generic_to_shared(p);
}

#define CP16(saddr, gptr) \
    asm volatile("cp.async.cg.shared.global [%0], [%1], 16;" :: "r"(saddr), "l"(gptr))
#define CP_COMMIT() asm volatile("cp.async.commit_group;")
#define CP_WAIT2()  asm volatile("cp.async.wait_group 2;" ::: "memory")
#define CP_WAIT0()  asm volatile("cp.async.wait_group 0;" ::: "memory")

#define MMA_BF16(d, a0, a1, a2, a3, b0, b1)                                       \
    asm volatile(                                                                 \
        "mma.sync.aligned.m16n8k16.row.col.f32.bf16.bf16.f32 "                    \
        "{%0,%1,%2,%3},{%4,%5,%6,%7},{%8,%9},{%0,%1,%2,%3};"                      \
        : "+f"((d)[0]), "+f"((d)[1]), "+f"((d)[2]), "+f"((d)[3])                  \
        : "r"(a0), "r"(a1), "r"(a2), "r"(a3), "r"(b0), "r"(b1))

#define LDSM_X4(r0, r1, r2, r3, addr)                                             \
    asm volatile("ldmatrix.sync.aligned.m8n8.x4.shared.b16 {%0,%1,%2,%3},[%4];"   \
        : "=r"(r0), "=r"(r1), "=r"(r2), "=r"(r3) : "r"(addr))

#define LDSM_X2(r0, r1, addr)                                                     \
    asm volatile("ldmatrix.sync.aligned.m8n8.x2.shared.b16 {%0,%1},[%2];"         \
        : "=r"(r0), "=r"(r1) : "r"(addr))

// ---------------------------------------------------------------------------
// split fp32 -> (bf16 hi, bf16 lo)
// ---------------------------------------------------------------------------
__global__ void __launch_bounds__(256) split_hl_kernel(const float* __restrict__ x,
                                                       bf16* __restrict__ hi,
                                                       bf16* __restrict__ lo) {
    const size_t i = ((size_t)blockIdx.x * 256 + threadIdx.x) * 4;
    float4 v = *(const float4*)(x + i);
    bf16 h0 = __float2bfloat16(v.x), h1 = __float2bfloat16(v.y);
    bf16 h2 = __float2bfloat16(v.z), h3 = __float2bfloat16(v.w);
    bf16 l0 = __float2bfloat16(v.x - __bfloat162float(h0));
    bf16 l1 = __float2bfloat16(v.y - __bfloat162float(h1));
    bf16 l2 = __float2bfloat16(v.z - __bfloat162float(h2));
    bf16 l3 = __float2bfloat16(v.w - __bfloat162float(h3));
    __nv_bfloat162* ph = (__nv_bfloat162*)(hi + i);
    __nv_bfloat162* pl = (__nv_bfloat162*)(lo + i);
    ph[0] = __nv_bfloat162{h0, h1}; ph[1] = __nv_bfloat162{h2, h3};
    pl[0] = __nv_bfloat162{l0, l1}; pl[1] = __nv_bfloat162{l2, l3};
}

// RE [257,512] -> padded [384,512] hi/lo (rows >=257 zero)
__global__ void __launch_bounds__(128) split_re_kernel(const float* __restrict__ RE,
                                                       bf16* __restrict__ REh,
                                                       bf16* __restrict__ REl) {
    const int row = blockIdx.x;
    const int c = threadIdx.x * 4;
    bf16 h[4] = {}, l[4] = {};
    if (row < NREL) {
        float4 v = *(const float4*)(RE + (size_t)row * DIM + c);
        h[0] = __float2bfloat16(v.x); l[0] = __float2bfloat16(v.x - __bfloat162float(h[0]));
        h[1] = __float2bfloat16(v.y); l[1] = __float2bfloat16(v.y - __bfloat162float(h[1]));
        h[2] = __float2bfloat16(v.z); l[2] = __float2bfloat16(v.z - __bfloat162float(h[2]));
        h[3] = __float2bfloat16(v.w); l[3] = __float2bfloat16(v.w - __bfloat162float(h[3]));
    }
    *(float2*)(REh + (size_t)row * DIM + c) = *(float2*)h;
    *(float2*)(REl + (size_t)row * DIM + c) = *(float2*)l;
}

// ---------------------------------------------------------------------------
// V [b][k][n] -> Vt hi/lo [b][n][k]
// ---------------------------------------------------------------------------
__global__ void __launch_bounds__(256) split_v_t_kernel(const float* __restrict__ V,
                                                        bf16* __restrict__ Vth,
                                                        bf16* __restrict__ Vtl) {
    __shared__ float t[32][33];
    const int b = blockIdx.z;
    const int k0 = blockIdx.x * 32;
    const int n0 = blockIdx.y * 32;
    const int tx = threadIdx.x;
    const int ty = threadIdx.y;
    const float* Vb = V + (size_t)b * SKL * DIM;

    #pragma unroll
    for (int i = 0; i < 4; i++)
        t[ty + i * 8][tx] = Vb[(size_t)(k0 + ty + i * 8) * DIM + n0 + tx];
    __syncthreads();

    #pragma unroll
    for (int i = 0; i < 4; i++) {
        float v = t[tx][ty + i * 8];
        bf16 h = __float2bfloat16(v);
        bf16 l = __float2bfloat16(v - __bfloat162float(h));
        size_t idx = (size_t)b * DIM * SKL + (size_t)(n0 + ty + i * 8) * SKL + k0 + tx;
        Vth[idx] = h;
        Vtl[idx] = l;
    }
}

// ---------------------------------------------------------------------------
// Multi-stage mma.sync GEMM: CTA 128x128, warp 64x32, 8 warps, 2 CTA/SM.
// 4-stage cp.async pipeline, BK=16, wait_group 2.
// C[m][n] = sum_k A[m,k]*B[n,k], bf16 hi/lo 3-term.
// smem/stage: 4 mats x 128 rows x 24 elems (48B rows, conflict-free LDSM).
// ---------------------------------------------------------------------------
#define MS_STAGES 4
#define MS_ROWLEN 24                       // elems per row (16 data + 8 pad)
#define MS_MAT    (128 * MS_ROWLEN * 2)    // 6144 B per matrix
#define MS_STAGE  (4 * MS_MAT)             // 24576 B per stage
#define MS_SMEM   (MS_STAGES * MS_STAGE)   // 98304 B

template<bool SCORES>
__global__ void __launch_bounds__(256, 2) mma_gemm_ms(
    const bf16* __restrict__ Ah, const bf16* __restrict__ Al,
    const bf16* __restrict__ Bh, const bf16* __restrict__ Bl,
    float* __restrict__ C, int kdim,
    size_t aBatch, size_t bBatch, size_t cBatch, int ldc)
{
    extern __shared__ __align__(16) char sm[];
    const uint32_t sbase = smem_u32(sm);

    const int tid = threadIdx.x;
    const int lane = tid & 31;
    const int wid = tid >> 5;
    const int wm = (wid >> 2) * 64;
    const int wn = (wid & 3) * 32;
    const int l4 = lane >> 2;
    const int q2 = (lane & 3) * 2;

    const int b = blockIdx.z;
    const int m0 = blockIdx.x * 128;
    const int n0 = blockIdx.y * 128;

    const bf16* gAh = Ah + (size_t)b * aBatch;
    const bf16* gAl = Al + (size_t)b * aBatch;
    const bf16* gBh = Bh + (size_t)b * bBatch;
    const bf16* gBl = Bl + (size_t)b * bBatch;

    // loader: each thread does 1 CP16 per matrix per stage
    const int lr = tid >> 1;            // 0..127
    const int lc = (tid & 1) << 3;      // 0 or 8
    const uint32_t lso = (uint32_t)(lr * MS_ROWLEN + lc) * 2;

    auto load_stage = [&](int stage, int k0) {
        const uint32_t st = sbase + stage * MS_STAGE + lso;
        const size_t ga = (size_t)(m0 + lr) * kdim + k0 + lc;
        const size_t gb = (size_t)(n0 + lr) * kdim + k0 + lc;
        CP16(st,              gAh + ga);
        CP16(st + MS_MAT,     gAl + ga);
        CP16(st + 2 * MS_MAT, gBh + gb);
        CP16(st + 3 * MS_MAT, gBl + gb);
        CP_COMMIT();
    };

    // ldmatrix per-thread byte offsets (within one matrix buffer)
    uint32_t aoff[4], boff[4];
    {
        const int ra = (lane & 15);
        const int ca = (lane >> 4) << 3;
        #pragma unroll
        for (int mf = 0; mf < 4; mf++)
            aoff[mf] = (uint32_t)(((wm + mf * 16 + ra) * MS_ROWLEN + ca) * 2);
        const int rb = (lane & 7);
        const int cb = ((lane >> 3) & 1) << 3;
        #pragma unroll
        for (int nf = 0; nf < 4; nf++)
            boff[nf] = (uint32_t)(((wn + nf * 8 + rb) * MS_ROWLEN + cb) * 2);
    }

    float acc[4][4][4] = {};

    const int S = kdim >> 4;   // number of k16 stages
    load_stage(0, 0);
    load_stage(1, 16);
    load_stage(2, 32);

    for (int s = 0; s < S; s++) {
        CP_WAIT2();
        __syncthreads();

        if (s + 3 < S) load_stage((s + 3) & 3, (s + 3) << 4);

        const uint32_t st = sbase + (s & 3) * MS_STAGE;
        uint32_t ah[4][4], al[4][4];
        #pragma unroll
        for (int mf = 0; mf < 4; mf++) {
            LDSM_X4(ah[mf][0], ah[mf][1], ah[mf][2], ah[mf][3], st + aoff[mf]);
            LDSM_X4(al[mf][0], al[mf][1], al[mf][2], al[mf][3], st + MS_MAT + aoff[mf]);
        }
        #pragma unroll
        for (int nf = 0; nf < 4; nf++) {
            uint32_t bh0, bh1, bl0, bl1;
            LDSM_X2(bh0, bh1, st + 2 * MS_MAT + boff[nf]);
            LDSM_X2(bl0, bl1, st + 3 * MS_MAT + boff[nf]);
            #pragma unroll
            for (int mf = 0; mf < 4; mf++) {
                MMA_BF16(acc[mf][nf], ah[mf][0], ah[mf][1], ah[mf][2], ah[mf][3], bh0, bh1);
                MMA_BF16(acc[mf][nf], ah[mf][0], ah[mf][1], ah[mf][2], ah[mf][3], bl0, bl1);
                MMA_BF16(acc[mf][nf], al[mf][0], al[mf][1], al[mf][2], al[mf][3], bh0, bh1);
            }
        }
        __syncthreads();
    }

    float* Cb = C + (size_t)b * cBatch;
    const float inv_norm = 0.04419417382415922f;   // 1/sqrt(512)

    #pragma unroll
    for (int mf = 0; mf < 4; mf++) {
        const int q0 = m0 + wm + mf * 16 + l4;
        const int q1 = q0 + 8;
        #pragma unroll
        for (int nf = 0; nf < 4; nf++) {
            const int col = n0 + wn + nf * 8 + q2;
            float* d = acc[mf][nf];
            if (SCORES) {
                const float* qr0 = g_qrel + ((size_t)b * SQL + q0) * NRELP;
                const float* qr1 = qr0 + (size_t)8 * NRELP;
                int r00 = min(RAD, max(-RAD, col - q0)) + RAD;
                int r01 = min(RAD, max(-RAD, col + 1 - q0)) + RAD;
                int r10 = min(RAD, max(-RAD, col - q1)) + RAD;
                int r11 = min(RAD, max(-RAD, col + 1 - q1)) + RAD;
                *(float2*)(Cb + (size_t)q0 * ldc + col) =
                    make_float2((d[0] + qr0[r00]) * inv_norm, (d[1] + qr0[r01]) * inv_norm);
                *(float2*)(Cb + (size_t)q1 * ldc + col) =
                    make_float2((d[2] + qr1[r10]) * inv_norm, (d[3] + qr1[r11]) * inv_norm);
            } else {
                *(float2*)(Cb + (size_t)q0 * ldc + col) = make_float2(d[0], d[1]);
                *(float2*)(Cb + (size_t)q1 * ldc + col) = make_float2(d[2], d[3]);
            }
        }
    }
}

// ---------------------------------------------------------------------------
// Row softmax (in place, fp32) + write bf16 hi/lo split of attn
// ---------------------------------------------------------------------------
__global__ void __launch_bounds__(256) softmax_split_kernel(float* __restrict__ attn) {
    __shared__ float red[8];
    float* p = attn + (size_t)blockIdx.x * SKL;
    const size_t gbase = (size_t)blockIdx.x * SKL;
    const int t = threadIdx.x;

    float v[8];
    float mx = -1e30f;
    #pragma unroll
    for (int i = 0; i < 8; i++) {
        v[i] = p[t + i * 256];
        mx = fmaxf(mx, v[i]);
    }
    #pragma unroll
    for (int o = 16; o > 0; o >>= 1) mx = fmaxf(mx, __shfl_xor_sync(0xffffffffu, mx, o));
    if ((t & 31) == 0) red[t >> 5] = mx;
    __syncthreads();
    float bmx = red[0];
    #pragma unroll
    for (int i = 1; i < 8; i++) bmx = fmaxf(bmx, red[i]);
    __syncthreads();

    float s = 0.f;
    #pragma unroll
    for (int i = 0; i < 8; i++) {
        v[i] = __expf(v[i] - bmx);
        s += v[i];
    }
    #pragma unroll
    for (int o = 16; o > 0; o >>= 1) s += __shfl_xor_sync(0xffffffffu, s, o);
    if ((t & 31) == 0) red[t >> 5] = s;
    __syncthreads();
    float tot = 0.f;
    #pragma unroll
    for (int i = 0; i < 8; i++) tot += red[i];
    const float inv = 1.0f / tot;

    #pragma unroll
    for (int i = 0; i < 8; i++) {
        float val = v[i] * inv;
        p[t + i * 256] = val;
        bf16 h = __float2bfloat16(val);
        bf16 l = __float2bfloat16(val - __bfloat162float(h));
        g_Ah[gbase + t + i * 256] = h;
        g_Al[gbase + t + i * 256] = l;
    }
}

// ---------------------------------------------------------------------------
extern "C" void kernel_launch(void* const* d_in, const int* in_sizes, int n_in,
                              void* d_out, int out_size) {
    const float* Q  = (const float*)d_in[0];
    const float* K  = (const float*)d_in[1];
    const float* V  = (const float*)d_in[2];
    const float* RE = (const float*)d_in[3];

    float* attn = (float*)d_out;
    float* Z    = attn + (size_t)NB * SQL * SKL;

    bf16 *Qh, *Ql, *Kh, *Kl, *REh, *REl, *Vth, *Vtl, *Ahp, *Alp;
    float* qrel;
    cudaGetSymbolAddress((void**)&Qh,  g_Qh);
    cudaGetSymbolAddress((void**)&Ql,  g_Ql);
    cudaGetSymbolAddress((void**)&Kh,  g_Kh);
    cudaGetSymbolAddress((void**)&Kl,  g_Kl);
    cudaGetSymbolAddress((void**)&REh, g_REh);
    cudaGetSymbolAddress((void**)&REl, g_REl);
    cudaGetSymbolAddress((void**)&Vth, g_Vth);
    cudaGetSymbolAddress((void**)&Vtl, g_Vtl);
    cudaGetSymbolAddress((void**)&Ahp, g_Ah);
    cudaGetSymbolAddress((void**)&Alp, g_Al);
    cudaGetSymbolAddress((void**)&qrel, g_qrel);

    cudaFuncSetAttribute(mma_gemm_ms<true>,
                         cudaFuncAttributeMaxDynamicSharedMemorySize, MS_SMEM);
    cudaFuncSetAttribute(mma_gemm_ms<false>,
                         cudaFuncAttributeMaxDynamicSharedMemorySize, MS_SMEM);

    // splits
    split_hl_kernel<<<(NB * SQL * DIM) / 1024, 256>>>(Q, Qh, Ql);
    split_hl_kernel<<<(NB * SKL * DIM) / 1024, 256>>>(K, Kh, Kl);
    split_re_kernel<<<NRELP, 128>>>(RE, REh, REl);
    {
        dim3 grid(SKL / 32, DIM / 32, NB);
        split_v_t_kernel<<<grid, dim3(32, 8)>>>(V, Vth, Vtl);
    }
    // Q_rel = Q @ RE^T  (batch folded into M)
    {
        dim3 grid((NB * SQL) / 128, NRELP / 128, 1);
        mma_gemm_ms<false><<<grid, 256, MS_SMEM>>>(
            Qh, Ql, REh, REl, qrel, DIM, 0, 0, 0, NRELP);
    }
    // scores = (Q@K^T + relpos) / sqrt(d) -> attn region
    {
        dim3 grid(SQL / 128, SKL / 128, NB);
        mma_gemm_ms<true><<<grid, 256, MS_SMEM>>>(
            Qh, Ql, Kh, Kl, attn, DIM,
            (size_t)SQL * DIM, (size_t)SKL * DIM, (size_t)SQL * SKL, SKL);
    }
    // softmax + split
    softmax_split_kernel<<<NB * SQL, 256>>>(attn);
    // Z = attn @ V
    {
        dim3 grid(SQL / 128, DIM / 128, NB);
        mma_gemm_ms<false><<<grid, 256, MS_SMEM>>>(
            Ahp, Alp, Vth, Vtl, Z, SKL,
            (size_t)SQL * SKL, (size_t)DIM * SKL, (size_t)SQL * DIM, DIM);
    }
}

// round 9
// speedup vs baseline: 1.1650x; 1.1650x over previous
#include <cuda_runtime.h>
#include <cuda_bf16.h>
#include <cstdint>

using bf16 = __nv_bfloat16;

#define NB   4
#define SQL  2048
#define SKL  2048
#define DIM  512
#define RAD  128
#define NREL 257
#define NRELP 384   // padded

// ---------------- device scratch ----------------
__device__ float g_qrel[(size_t)NB * SQL * NRELP];
__device__ bf16 g_Qh[(size_t)NB * SQL * DIM];
__device__ bf16 g_Ql[(size_t)NB * SQL * DIM];
__device__ bf16 g_Kh[(size_t)NB * SKL * DIM];
__device__ bf16 g_Kl[(size_t)NB * SKL * DIM];
__device__ bf16 g_REh[(size_t)NRELP * DIM];
__device__ bf16 g_REl[(size_t)NRELP * DIM];
__device__ bf16 g_Vth[(size_t)NB * DIM * SKL];   // V transposed: [b][n][k]
__device__ bf16 g_Vtl[(size_t)NB * DIM * SKL];
__device__ bf16 g_Ah[(size_t)NB * SQL * SKL];    // attn split
__device__ bf16 g_Al[(size_t)NB * SQL * SKL];

// ---------------- helpers ----------------
__device__ __forceinline__ uint32_t smem_u32(const void* p) {
    return (uint32_t)__cvta_generic_to_shared(p);
}

#define CP16(saddr, gptr) \
    asm volatile("cp.async.cg.shared.global [%0], [%1], 16;" :: "r"(saddr), "l"(gptr))
#define CP_COMMIT() asm volatile("cp.async.commit_group;")
#define CP_WAIT0()  asm volatile("cp.async.wait_group 0;" ::: "memory")

#define MMA_BF16(d, a0, a1, a2, a3, b0, b1)                                       \
    asm volatile(                                                                 \
        "mma.sync.aligned.m16n8k16.row.col.f32.bf16.bf16.f32 "                    \
        "{%0,%1,%2,%3},{%4,%5,%6,%7},{%8,%9},{%0,%1,%2,%3};"                      \
        : "+f"((d)[0]), "+f"((d)[1]), "+f"((d)[2]), "+f"((d)[3])                  \
        : "r"(a0), "r"(a1), "r"(a2), "r"(a3), "r"(b0), "r"(b1))

#define LDSM_X4(r0, r1, r2, r3, addr)                                             \
    asm volatile("ldmatrix.sync.aligned.m8n8.x4.shared.b16 {%0,%1,%2,%3},[%4];"   \
        : "=r"(r0), "=r"(r1), "=r"(r2), "=r"(r3) : "r"(addr))

// ---------------------------------------------------------------------------
// split fp32 -> (bf16 hi, bf16 lo)
// ---------------------------------------------------------------------------
__global__ void __launch_bounds__(256) split_hl_kernel(const float* __restrict__ x,
                                                       bf16* __restrict__ hi,
                                                       bf16* __restrict__ lo) {
    const size_t i = ((size_t)blockIdx.x * 256 + threadIdx.x) * 4;
    float4 v = *(const float4*)(x + i);
    bf16 h0 = __float2bfloat16(v.x), h1 = __float2bfloat16(v.y);
    bf16 h2 = __float2bfloat16(v.z), h3 = __float2bfloat16(v.w);
    bf16 l0 = __float2bfloat16(v.x - __bfloat162float(h0));
    bf16 l1 = __float2bfloat16(v.y - __bfloat162float(h1));
    bf16 l2 = __float2bfloat16(v.z - __bfloat162float(h2));
    bf16 l3 = __float2bfloat16(v.w - __bfloat162float(h3));
    __nv_bfloat162* ph = (__nv_bfloat162*)(hi + i);
    __nv_bfloat162* pl = (__nv_bfloat162*)(lo + i);
    ph[0] = __nv_bfloat162{h0, h1}; ph[1] = __nv_bfloat162{h2, h3};
    pl[0] = __nv_bfloat162{l0, l1}; pl[1] = __nv_bfloat162{l2, l3};
}

// RE [257,512] -> padded [384,512] hi/lo (rows >=257 zero)
__global__ void __launch_bounds__(128) split_re_kernel(const float* __restrict__ RE,
                                                       bf16* __restrict__ REh,
                                                       bf16* __restrict__ REl) {
    const int row = blockIdx.x;
    const int c = threadIdx.x * 4;
    bf16 h[4] = {}, l[4] = {};
    if (row < NREL) {
        float4 v = *(const float4*)(RE + (size_t)row * DIM + c);
        h[0] = __float2bfloat16(v.x); l[0] = __float2bfloat16(v.x - __bfloat162float(h[0]));
        h[1] = __float2bfloat16(v.y); l[1] = __float2bfloat16(v.y - __bfloat162float(h[1]));
        h[2] = __float2bfloat16(v.z); l[2] = __float2bfloat16(v.z - __bfloat162float(h[2]));
        h[3] = __float2bfloat16(v.w); l[3] = __float2bfloat16(v.w - __bfloat162float(h[3]));
    }
    *(float2*)(REh + (size_t)row * DIM + c) = *(float2*)h;
    *(float2*)(REl + (size_t)row * DIM + c) = *(float2*)l;
}

// ---------------------------------------------------------------------------
// V [b][k][n] -> Vt hi/lo [b][n][k]
// ---------------------------------------------------------------------------
__global__ void __launch_bounds__(256) split_v_t_kernel(const float* __restrict__ V,
                                                        bf16* __restrict__ Vth,
                                                        bf16* __restrict__ Vtl) {
    __shared__ float t[32][33];
    const int b = blockIdx.z;
    const int k0 = blockIdx.x * 32;
    const int n0 = blockIdx.y * 32;
    const int tx = threadIdx.x;
    const int ty = threadIdx.y;
    const float* Vb = V + (size_t)b * SKL * DIM;

    #pragma unroll
    for (int i = 0; i < 4; i++)
        t[ty + i * 8][tx] = Vb[(size_t)(k0 + ty + i * 8) * DIM + n0 + tx];
    __syncthreads();

    #pragma unroll
    for (int i = 0; i < 4; i++) {
        float v = t[tx][ty + i * 8];
        bf16 h = __float2bfloat16(v);
        bf16 l = __float2bfloat16(v - __bfloat162float(h));
        size_t idx = (size_t)b * DIM * SKL + (size_t)(n0 + ty + i * 8) * SKL + k0 + tx;
        Vth[idx] = h;
        Vtl[idx] = l;
    }
}

// ---------------------------------------------------------------------------
// Tensor-core GEMM (bf16 hi/lo, 3 MMA terms): C[m][n] = sum_k A[m,k]*B[n,k]
// 128x128x32 tile, 8 warps (warp 64x32), cp.async double buffer, ldmatrix.
// MMA ordering: term-middle loop -> same-acc reuse distance 8 (hides HMMA lat).
// ---------------------------------------------------------------------------
template<int KDIM, bool SCORES>
__global__ void __launch_bounds__(256, 2) mma_gemm_kernel(
    const bf16* __restrict__ Ah, const bf16* __restrict__ Al,
    const bf16* __restrict__ Bh, const bf16* __restrict__ Bl,
    float* __restrict__ C,
    size_t aBatch, size_t bBatch, size_t cBatch, int ldc)
{
    extern __shared__ __align__(16) bf16 sm[];
    bf16* sAh = sm;                 // [2][128][40]
    bf16* sAl = sm + 10240;
    bf16* sBh = sm + 20480;
    bf16* sBl = sm + 30720;

    const int tid = threadIdx.x;
    const int lane = tid & 31;
    const int wid = tid >> 5;
    const int wm = (wid >> 2) * 64;
    const int wn = (wid & 3) * 32;
    const int l4 = lane >> 2;
    const int q2 = (lane & 3) * 2;

    const int b = blockIdx.z;
    const int m0 = blockIdx.x * 128;
    const int n0 = blockIdx.y * 128;

    const bf16* gAh = Ah + (size_t)b * aBatch;
    const bf16* gAl = Al + (size_t)b * aBatch;
    const bf16* gBh = Bh + (size_t)b * bBatch;
    const bf16* gBl = Bl + (size_t)b * bBatch;

    auto load_stage = [&](int buf, int k0) {
        #pragma unroll
        for (int p = 0; p < 2; p++) {
            int idx = tid + p * 256;
            int r = idx >> 2;
            int c = (idx & 3) << 3;
            size_t ga = (size_t)(m0 + r) * KDIM + k0 + c;
            size_t gb = (size_t)(n0 + r) * KDIM + k0 + c;
            int so = buf * 5120 + r * 40 + c;
            CP16(smem_u32(sAh + so), gAh + ga);
            CP16(smem_u32(sAl + so), gAl + ga);
            CP16(smem_u32(sBh + so), gBh + gb);
            CP16(smem_u32(sBl + so), gBl + gb);
        }
        CP_COMMIT();
    };

    // ldmatrix per-thread base byte offsets (within a buffer, excluding kk)
    uint32_t aoff[4], boff[2];
    {
        const int ra = (lane & 15);
        const int ca = (lane >> 4) << 3;
        #pragma unroll
        for (int mf = 0; mf < 4; mf++)
            aoff[mf] = (uint32_t)(((wm + mf * 16 + ra) * 40 + ca) * 2);
        // B x4: mats {(n,k0),(n,k8),(n+8,k0),(n+8,k8)} per 16-row group
        const int rb = (lane & 7) + ((lane >> 4) & 1) * 8;
        const int cb = ((lane >> 3) & 1) << 3;
        #pragma unroll
        for (int np = 0; np < 2; np++)
            boff[np] = (uint32_t)(((wn + np * 16 + rb) * 40 + cb) * 2);
    }
    const uint32_t uAh = smem_u32(sAh), uAl = smem_u32(sAl);
    const uint32_t uBh = smem_u32(sBh), uBl = smem_u32(sBl);

    float acc[4][4][4] = {};

    load_stage(0, 0);
    CP_WAIT0();
    __syncthreads();

    int buf = 0;
    for (int k0 = 0; k0 < KDIM; k0 += 32) {
        const bool has_next = (k0 + 32) < KDIM;
        if (has_next) load_stage(buf ^ 1, k0 + 32);

        #pragma unroll
        for (int kk = 0; kk < 32; kk += 16) {
            const uint32_t kb = (uint32_t)(buf * 10240 + kk * 2);
            uint32_t ah[4][4], al[4][4];
            #pragma unroll
            for (int mf = 0; mf < 4; mf++) {
                LDSM_X4(ah[mf][0], ah[mf][1], ah[mf][2], ah[mf][3], uAh + kb + aoff[mf]);
                LDSM_X4(al[mf][0], al[mf][1], al[mf][2], al[mf][3], uAl + kb + aoff[mf]);
            }
            #pragma unroll
            for (int np = 0; np < 2; np++) {
                uint32_t bh[4], bl[4];
                LDSM_X4(bh[0], bh[1], bh[2], bh[3], uBh + kb + boff[np]);
                LDSM_X4(bl[0], bl[1], bl[2], bl[3], uBl + kb + boff[np]);
                // term-middle ordering: acc reuse distance = 8 MMAs
                #pragma unroll
                for (int t = 0; t < 3; t++) {
                    const uint32_t* bb = (t == 1) ? bl : bh;
                    #pragma unroll
                    for (int nf2 = 0; nf2 < 2; nf2++) {
                        const int nf = np * 2 + nf2;
                        const uint32_t b0 = bb[nf2 * 2], b1 = bb[nf2 * 2 + 1];
                        #pragma unroll
                        for (int mf = 0; mf < 4; mf++) {
                            if (t == 2) {
                                MMA_BF16(acc[mf][nf], al[mf][0], al[mf][1], al[mf][2], al[mf][3], b0, b1);
                            } else {
                                MMA_BF16(acc[mf][nf], ah[mf][0], ah[mf][1], ah[mf][2], ah[mf][3], b0, b1);
                            }
                        }
                    }
                }
            }
        }

        if (has_next) CP_WAIT0();
        __syncthreads();
        buf ^= 1;
    }

    float* Cb = C + (size_t)b * cBatch;
    const float inv_norm = 0.04419417382415922f;   // 1/sqrt(512)

    #pragma unroll
    for (int mf = 0; mf < 4; mf++) {
        const int q0 = m0 + wm + mf * 16 + l4;
        const int q1 = q0 + 8;
        #pragma unroll
        for (int nf = 0; nf < 4; nf++) {
            const int col = n0 + wn + nf * 8 + q2;
            float* d = acc[mf][nf];
            if (SCORES) {
                const float* qr0 = g_qrel + ((size_t)b * SQL + q0) * NRELP;
                const float* qr1 = qr0 + (size_t)8 * NRELP;
                int r00 = min(RAD, max(-RAD, col - q0)) + RAD;
                int r01 = min(RAD, max(-RAD, col + 1 - q0)) + RAD;
                int r10 = min(RAD, max(-RAD, col - q1)) + RAD;
                int r11 = min(RAD, max(-RAD, col + 1 - q1)) + RAD;
                *(float2*)(Cb + (size_t)q0 * ldc + col) =
                    make_float2((d[0] + qr0[r00]) * inv_norm, (d[1] + qr0[r01]) * inv_norm);
                *(float2*)(Cb + (size_t)q1 * ldc + col) =
                    make_float2((d[2] + qr1[r10]) * inv_norm, (d[3] + qr1[r11]) * inv_norm);
            } else {
                *(float2*)(Cb + (size_t)q0 * ldc + col) = make_float2(d[0], d[1]);
                *(float2*)(Cb + (size_t)q1 * ldc + col) = make_float2(d[2], d[3]);
            }
        }
    }
}

// ---------------------------------------------------------------------------
// Row softmax (in place, fp32) + write bf16 hi/lo split of attn
// ---------------------------------------------------------------------------
__global__ void __launch_bounds__(256) softmax_split_kernel(float* __restrict__ attn) {
    __shared__ float red[8];
    float* p = attn + (size_t)blockIdx.x * SKL;
    const size_t gbase = (size_t)blockIdx.x * SKL;
    const int t = threadIdx.x;

    float v[8];
    float mx = -1e30f;
    #pragma unroll
    for (int i = 0; i < 8; i++) {
        v[i] = p[t + i * 256];
        mx = fmaxf(mx, v[i]);
    }
    #pragma unroll
    for (int o = 16; o > 0; o >>= 1) mx = fmaxf(mx, __shfl_xor_sync(0xffffffffu, mx, o));
    if ((t & 31) == 0) red[t >> 5] = mx;
    __syncthreads();
    float bmx = red[0];
    #pragma unroll
    for (int i = 1; i < 8; i++) bmx = fmaxf(bmx, red[i]);
    __syncthreads();

    float s = 0.f;
    #pragma unroll
    for (int i = 0; i < 8; i++) {
        v[i] = __expf(v[i] - bmx);
        s += v[i];
    }
    #pragma unroll
    for (int o = 16; o > 0; o >>= 1) s += __shfl_xor_sync(0xffffffffu, s, o);
    if ((t & 31) == 0) red[t >> 5] = s;
    __syncthreads();
    float tot = 0.f;
    #pragma unroll
    for (int i = 0; i < 8; i++) tot += red[i];
    const float inv = 1.0f / tot;

    #pragma unroll
    for (int i = 0; i < 8; i++) {
        float val = v[i] * inv;
        p[t + i * 256] = val;
        bf16 h = __float2bfloat16(val);
        bf16 l = __float2bfloat16(val - __bfloat162float(h));
        g_Ah[gbase + t + i * 256] = h;
        g_Al[gbase + t + i * 256] = l;
    }
}

// ---------------------------------------------------------------------------
extern "C" void kernel_launch(void* const* d_in, const int* in_sizes, int n_in,
                              void* d_out, int out_size) {
    const float* Q  = (const float*)d_in[0];
    const float* K  = (const float*)d_in[1];
    const float* V  = (const float*)d_in[2];
    const float* RE = (const float*)d_in[3];

    float* attn = (float*)d_out;
    float* Z    = attn + (size_t)NB * SQL * SKL;

    bf16 *Qh, *Ql, *Kh, *Kl, *REh, *REl, *Vth, *Vtl, *Ahp, *Alp;
    float* qrel;
    cudaGetSymbolAddress((void**)&Qh,  g_Qh);
    cudaGetSymbolAddress((void**)&Ql,  g_Ql);
    cudaGetSymbolAddress((void**)&Kh,  g_Kh);
    cudaGetSymbolAddress((void**)&Kl,  g_Kl);
    cudaGetSymbolAddress((void**)&REh, g_REh);
    cudaGetSymbolAddress((void**)&REl, g_REl);
    cudaGetSymbolAddress((void**)&Vth, g_Vth);
    cudaGetSymbolAddress((void**)&Vtl, g_Vtl);
    cudaGetSymbolAddress((void**)&Ahp, g_Ah);
    cudaGetSymbolAddress((void**)&Alp, g_Al);
    cudaGetSymbolAddress((void**)&qrel, g_qrel);

    const int SMEM_GEMM = 81920;
    cudaFuncSetAttribute(mma_gemm_kernel<DIM, true>,
                         cudaFuncAttributeMaxDynamicSharedMemorySize, SMEM_GEMM);
    cudaFuncSetAttribute(mma_gemm_kernel<DIM, false>,
                         cudaFuncAttributeMaxDynamicSharedMemorySize, SMEM_GEMM);
    cudaFuncSetAttribute(mma_gemm_kernel<SKL, false>,
                         cudaFuncAttributeMaxDynamicSharedMemorySize, SMEM_GEMM);

    // splits
    split_hl_kernel<<<(NB * SQL * DIM) / 1024, 256>>>(Q, Qh, Ql);
    split_hl_kernel<<<(NB * SKL * DIM) / 1024, 256>>>(K, Kh, Kl);
    split_re_kernel<<<NRELP, 128>>>(RE, REh, REl);
    {
        dim3 grid(SKL / 32, DIM / 32, NB);
        split_v_t_kernel<<<grid, dim3(32, 8)>>>(V, Vth, Vtl);
    }
    // Q_rel = Q @ RE^T  (batch folded into M)
    {
        dim3 grid((NB * SQL) / 128, NRELP / 128, 1);
        mma_gemm_kernel<DIM, false><<<grid, 256, SMEM_GEMM>>>(
            Qh, Ql, REh, REl, qrel, 0, 0, 0, NRELP);
    }
    // scores = (Q@K^T + relpos) / sqrt(d) -> attn region
    {
        dim3 grid(SQL / 128, SKL / 128, NB);
        mma_gemm_kernel<DIM, true><<<grid, 256, SMEM_GEMM>>>(
            Qh, Ql, Kh, Kl, attn,
            (size_t)SQL * DIM, (size_t)SKL * DIM, (size_t)SQL * SKL, SKL);
    }
    // softmax + split
    softmax_split_kernel<<<NB * SQL, 256>>>(attn);
    // Z = attn @ V
    {
        dim3 grid(SQL / 128, DIM / 128, NB);
        mma_gemm_kernel<SKL, false><<<grid, 256, SMEM_GEMM>>>(
            Ahp, Alp, Vth, Vtl, Z,
            (size_t)SQL * SKL, (size_t)DIM * SKL, (size_t)SQL * DIM, DIM);
    }
}